// round 15
// baseline (speedup 1.0000x reference)
#include <cuda_runtime.h>
#include <cuda_fp16.h>
#include <cstdint>

#define NN 100000
#define D  256
#define NE 1600000
#define CAP 128
#define MAXOVF 65536

typedef __half fp16;

// ---------------- scratch (device globals: allocations are forbidden) -------
__device__ fp16  g_xh [(size_t)NN * D];
__device__ fp16  g_ah [(size_t)NN * D];
__device__ fp16  g_h1h[(size_t)NN * D];
__device__ fp16  g_h2h[(size_t)NN * D];
__device__ fp16  g_wtf[5 * 65536];            // transposed weights [N][K], fp16
__device__ int   g_cnt[NN];
__device__ int   g_srclist[(size_t)NN * CAP];
__device__ int   g_ovf[2 * MAXOVF];
__device__ int   g_novf;
__device__ int   g_is64;

// ---------------- helpers ----------------------------------------------------
__device__ __forceinline__ uint32_t smem_u32(const void* p) {
    uint32_t a;
    asm("{ .reg .u64 t; cvta.to.shared.u64 t, %1; cvt.u32.u64 %0, t; }"
        : "=r"(a) : "l"(p));
    return a;
}
__device__ __forceinline__ void cp16(uint32_t dst, const void* src, int sz) {
    asm volatile("cp.async.cg.shared.global [%0], [%1], 16, %2;"
                 :: "r"(dst), "l"(src), "r"(sz) : "memory");
}
__device__ __forceinline__ void cp_commit() {
    asm volatile("cp.async.commit_group;" ::: "memory");
}
template<int N>
__device__ __forceinline__ void cp_wait() {
    asm volatile("cp.async.wait_group %0;" :: "n"(N) : "memory");
}
__device__ __forceinline__ void ldsm4(uint32_t* r, uint32_t addr) {
    asm volatile("ldmatrix.sync.aligned.m8n8.x4.shared.b16 {%0,%1,%2,%3}, [%4];"
                 : "=r"(r[0]), "=r"(r[1]), "=r"(r[2]), "=r"(r[3]) : "r"(addr));
}
__device__ __forceinline__ void mma16816(float* c, const uint32_t* a, const uint32_t* b) {
    asm volatile("mma.sync.aligned.m16n8k16.row.col.f32.f16.f16.f32 "
                 "{%0,%1,%2,%3}, {%4,%5,%6,%7}, {%8,%9}, {%0,%1,%2,%3};"
                 : "+f"(c[0]), "+f"(c[1]), "+f"(c[2]), "+f"(c[3])
                 : "r"(a[0]), "r"(a[1]), "r"(a[2]), "r"(a[3]),
                   "r"(b[0]), "r"(b[1]));
}
__device__ __forceinline__ uint32_t pack_h2(float a, float b) {
    __half2 t = __floats2half2_rn(a, b);
    return *reinterpret_cast<uint32_t*>(&t);
}
__device__ __forceinline__ float2 h2_to_f2(uint32_t u) {
    __half2 h = *reinterpret_cast<__half2*>(&u);
    return __half22float2(h);
}

// ---------------- setup (weights | zero cnt | probe) --------------------------
//   [0, 1280)      weight transpose+cast     (1280 * 256 = 5*65536)
//   [1280, 1671)   zero g_cnt
//   1671           dtype probe + novf reset
#define SETUP_WB   1280
#define SETUP_ZB   (SETUP_WB + 391)
#define SETUP_GRID (SETUP_ZB + 1)

__global__ void setup_kernel(const float* __restrict__ W1l, const float* __restrict__ W1r,
                             const float* __restrict__ W2l, const float* __restrict__ W2r,
                             const float* __restrict__ W3,
                             const int* __restrict__ w) {
    int b = blockIdx.x;
    int t = threadIdx.x;
    if (b < SETUP_WB) {
        int i = b * 256 + t;
        int m = i >> 16, idx = i & 65535;
        int n = idx >> 8, k = idx & 255;
        const float* W = (m == 0) ? W1l : (m == 1) ? W1r : (m == 2) ? W2l
                       : (m == 3) ? W2r : W3;
        g_wtf[i] = __float2half_rn(W[k * 256 + n]);
    } else if (b < SETUP_ZB) {
        int i = (b - SETUP_WB) * 256 + t;
        if (i < NN) g_cnt[i] = 0;
    } else if (t == 0) {
        int all_zero = 1;
        for (int i = 1; i < 128; i += 2)
            if (w[i] != 0) { all_zero = 0; break; }
        g_is64 = all_zero;
        g_novf = 0;
    }
}

// ---------------- fused build + x-cast ----------------------------------------
//   [0, 25000)       cast x -> fp16 (BW-bound; overlaps with edge atomics)
//   [25000, 31250)   edge bucket build (atomic-latency-bound)
#define BLD_XB   25000
#define BLD_EB   (BLD_XB + 6250)

__global__ void build_kernel(const float* __restrict__ x, const int* __restrict__ w) {
    int b = blockIdx.x;
    int t = threadIdx.x;
    if (b < BLD_XB) {
        size_t i = ((size_t)b * 256 + t) * 4;
        float4 v = *(const float4*)(x + i);
        *(uint2*)((fp16*)g_xh + i) = make_uint2(pack_h2(v.x, v.y), pack_h2(v.z, v.w));
        return;
    }
    int e = (b - BLD_XB) * 256 + t;
    if (e >= NE) return;
    int s, d;
    if (g_is64) { s = w[2 * e]; d = w[2 * (NE + e)]; }
    else        { s = w[e];     d = w[NE + e];       }
    int pos = atomicAdd(&g_cnt[d], 1);
    if (pos < CAP) {
        g_srclist[(size_t)d * CAP + pos] = s;
    } else {
        int o = atomicAdd(&g_novf, 1);
        if (o < MAXOVF) { g_ovf[2 * o] = s; g_ovf[2 * o + 1] = d; }
    }
}

// ---------------- gather aggregation -----------------------------------------
// Reads fp16 features (512B/row); accumulates fp32; writes fp16 mean.
// Overflow (deg > CAP) handled in-kernel: the owning warp scans g_ovf for its
// own dst and accumulates those sources too. Exact; never taken for this graph.
__global__ __launch_bounds__(256)
void aggregate_kernel(const fp16* __restrict__ fh, fp16* __restrict__ outh) {
    int warp = (blockIdx.x * blockDim.x + threadIdx.x) >> 5;
    int lane = threadIdx.x & 31;
    if (warp >= NN) return;
    int deg = g_cnt[warp];
    const int* lst = g_srclist + (size_t)warp * CAP;

    float a[8];
#pragma unroll
    for (int q = 0; q < 8; q++) a[q] = 0.f;

    int nIn = min(deg, CAP);
    for (int base = 0; base < nIn; base += 32) {
        int sv = 0;
        if (base + lane < nIn) sv = lst[base + lane];
        int cnt = min(nIn - base, 32);
#pragma unroll 4
        for (int j = 0; j < cnt; j++) {
            int sj = __shfl_sync(0xffffffffu, sv, j);
            uint4 v = ((const uint4*)(fh + (size_t)sj * D))[lane];
            float2 p;
            p = h2_to_f2(v.x); a[0] += p.x; a[1] += p.y;
            p = h2_to_f2(v.y); a[2] += p.x; a[3] += p.y;
            p = h2_to_f2(v.z); a[4] += p.x; a[5] += p.y;
            p = h2_to_f2(v.w); a[6] += p.x; a[7] += p.y;
        }
    }

    if (deg > CAP) {   // rare exact-repair path: pull my edges from g_ovf
        int n = min(g_novf, MAXOVF);
        for (int e = 0; e < n; e++) {
            if (g_ovf[2 * e + 1] == warp) {
                int sj = g_ovf[2 * e];
                uint4 v = ((const uint4*)(fh + (size_t)sj * D))[lane];
                float2 p;
                p = h2_to_f2(v.x); a[0] += p.x; a[1] += p.y;
                p = h2_to_f2(v.y); a[2] += p.x; a[3] += p.y;
                p = h2_to_f2(v.z); a[4] += p.x; a[5] += p.y;
                p = h2_to_f2(v.w); a[6] += p.x; a[7] += p.y;
            }
        }
    }

    float inv = 1.0f / fmaxf((float)deg, 1.0f);
#pragma unroll
    for (int q = 0; q < 8; q++) a[q] *= inv;

    uint4 hv = make_uint4(pack_h2(a[0], a[1]), pack_h2(a[2], a[3]),
                          pack_h2(a[4], a[5]), pack_h2(a[6], a[7]));
    *(uint4*)(outh + (size_t)warp * D + lane * 8) = hv;
}

// ---------------- mma.sync GEMM ----------------------------------------------
// CTA: 128 rows x 128 cols, grid (782, 2), 2 CTAs/SM (4 warps/SMSP).
// 8 warps (4m x 2n), warp tile 32x64.
// C = [relu]( A1@W1' (+ A2@W2') + bias ); plain fp16 operands, fp32 accumulate.
// 3-stage cp.async pipeline, one __syncthreads per iteration.
// Per k16: all 6 LDSM issued up-front (4-deep B lookahead), then 16 MMAs.
// Smem stage: A | B, each 128 rows x 64 k fp16, row stride 144B (conflict-free).
#define KC     64
#define ROWB   144
#define MAT    18432            // 128 * 144
#define STAGE  (2 * MAT)        // 36864
#define SMEMSZ (3 * STAGE)      // 110592

template<bool DUAL, bool RELU, bool F32OUT, bool F16OUT>
__global__ __launch_bounds__(256, 2)
void mma_gemm(const fp16* __restrict__ a1, const fp16* __restrict__ w1,
              const fp16* __restrict__ a2, const fp16* __restrict__ w2,
              const float* __restrict__ bias,
              float* __restrict__ Cf, fp16* __restrict__ Ch) {
    extern __shared__ char smem[];
    const uint32_t sb = smem_u32(smem);
    const int tid  = threadIdx.x;
    const int wid  = tid >> 5;
    const int lane = tid & 31;
    const int wm   = wid & 3;        // m strip: wm*32
    const int wn   = wid >> 2;       // n strip: wn*64
    const int m0   = blockIdx.x * 128;
    const int n0   = blockIdx.y * 128;

    float acc[2][8][4];
#pragma unroll
    for (int mi = 0; mi < 2; mi++)
#pragma unroll
        for (int ni = 0; ni < 8; ni++)
#pragma unroll
            for (int q = 0; q < 4; q++) acc[mi][ni][q] = 0.f;

    const int nIter = (DUAL ? 2 : 1) * 4;    // K chunks of 64

    auto prefetch = [&](int buf, int it) {
        const int rep   = it >> 2;
        const int kbase = (it & 3) * KC;
        const fp16* A = rep ? a2 : a1;
        const fp16* W = rep ? w2 : w1;
        const uint32_t bb = sb + buf * STAGE;
        // A: 128 rows x 8 chunks(16B) = 1024 slots; B same.
#pragma unroll
        for (int i = 0; i < 4; i++) {
            int q   = tid + i * 256;
            int row = q >> 3, c8 = q & 7;
            uint32_t dsto = (uint32_t)(row * ROWB + c8 * 16);
            int grow = m0 + row;
            int arow = grow < NN ? grow : 0;
            int sz   = grow < NN ? 16 : 0;
            cp16(bb + dsto, A + (size_t)arow * D + kbase + c8 * 8, sz);
            cp16(bb + MAT + dsto, W + (size_t)(n0 + row) * D + kbase + c8 * 8, 16);
        }
    };

    prefetch(0, 0);
    cp_commit();
    prefetch(1, 1);
    cp_commit();

    const int alr = lane & 15, akh = lane >> 4;                        // A lane map
    const int bnr = lane & 7, bkh = (lane >> 3) & 1, btl = lane >> 4;  // B lane map

    int buf = 0;
    for (int it = 0; it < nIter; it++) {
        if (it + 1 < nIter) cp_wait<1>();     // stage `it` landed
        else                cp_wait<0>();
        __syncthreads();                      // all warps done with stage it-1's buffer
        if (it + 2 < nIter) { prefetch((it + 2) % 3, it + 2); cp_commit(); }

        const uint32_t bb = sb + buf * STAGE;
        const uint32_t Ab = bb, Bb = bb + MAT;
        buf = (buf + 1 == 3) ? 0 : buf + 1;

#pragma unroll
        for (int k16 = 0; k16 < 4; k16++) {
            const uint32_t a_off = (uint32_t)((wm * 32 + alr) * ROWB + (k16 * 16 + akh * 8) * 2);
            const uint32_t b_off = (uint32_t)((wn * 64 + btl * 8 + bnr) * ROWB + (k16 * 16 + bkh * 8) * 2);

            uint32_t a0[4], a1r[4], br[16];
            ldsm4(a0,  Ab + a_off);
            ldsm4(a1r, Ab + a_off + 16 * ROWB);
            ldsm4(br +  0, Bb + b_off + 0 * 16 * ROWB);
            ldsm4(br +  4, Bb + b_off + 1 * 16 * ROWB);
            ldsm4(br +  8, Bb + b_off + 2 * 16 * ROWB);
            ldsm4(br + 12, Bb + b_off + 3 * 16 * ROWB);

#pragma unroll
            for (int nf = 0; nf < 4; nf++) {
                mma16816(acc[0][2 * nf + 0], a0,  br + 4 * nf);
                mma16816(acc[0][2 * nf + 1], a0,  br + 4 * nf + 2);
                mma16816(acc[1][2 * nf + 0], a1r, br + 4 * nf);
                mma16816(acc[1][2 * nf + 1], a1r, br + 4 * nf + 2);
            }
        }
    }

    // -------- epilogue --------
    const int rbase = m0 + wm * 32 + (lane >> 2);
    const int cbase = n0 + wn * 64 + (lane & 3) * 2;
#pragma unroll
    for (int ni = 0; ni < 8; ni++) {
        const int col = cbase + ni * 8;
        const float b0 = bias[col], b1 = bias[col + 1];
#pragma unroll
        for (int mi = 0; mi < 2; mi++) {
#pragma unroll
            for (int rr = 0; rr < 2; rr++) {
                int row = rbase + mi * 16 + rr * 8;
                if (row >= NN) continue;
                float v0 = acc[mi][ni][rr * 2 + 0] + b0;
                float v1 = acc[mi][ni][rr * 2 + 1] + b1;
                if (RELU) { v0 = fmaxf(v0, 0.f); v1 = fmaxf(v1, 0.f); }
                if (F32OUT)
                    *(float2*)(Cf + (size_t)row * D + col) = make_float2(v0, v1);
                if (F16OUT)
                    *(uint32_t*)(Ch + (size_t)row * D + col) = pack_h2(v0, v1);
            }
        }
    }
}

// ---------------- launch ------------------------------------------------------
extern "C" void kernel_launch(void* const* d_in, const int* in_sizes, int n_in,
                              void* d_out, int out_size) {
    const float* x   = (const float*)d_in[0];
    const int*   ei  = (const int*)d_in[1];
    const float* W1l = (const float*)d_in[2];
    const float* b1  = (const float*)d_in[3];
    const float* W1r = (const float*)d_in[4];
    const float* W2l = (const float*)d_in[5];
    const float* b2  = (const float*)d_in[6];
    const float* W2r = (const float*)d_in[7];
    const float* W3  = (const float*)d_in[8];
    const float* b3  = (const float*)d_in[9];
    float* out = (float*)d_out;

    fp16 *xh, *ah, *h1h, *h2h, *wtf;
    cudaGetSymbolAddress((void**)&xh,  g_xh);
    cudaGetSymbolAddress((void**)&ah,  g_ah);
    cudaGetSymbolAddress((void**)&h1h, g_h1h);
    cudaGetSymbolAddress((void**)&h2h, g_h2h);
    cudaGetSymbolAddress((void**)&wtf, g_wtf);

    cudaFuncSetAttribute(mma_gemm<true,  true,  false, true>,
                         cudaFuncAttributeMaxDynamicSharedMemorySize, SMEMSZ);
    cudaFuncSetAttribute(mma_gemm<false, false, true,  false>,
                         cudaFuncAttributeMaxDynamicSharedMemorySize, SMEMSZ);

    dim3 gemmGrid((NN + 127) / 128, 2);            // (782, 2)
    const int aggBlocks = (NN * 32 + 255) / 256;

    // ---- prep: setup (weights | zero | probe) then fused build+cast ----
    setup_kernel<<<SETUP_GRID, 256>>>(W1l, W1r, W2l, W2r, W3, ei);
    build_kernel<<<BLD_EB, 256>>>(x, ei);

    // ---- layer 1 ----
    aggregate_kernel<<<aggBlocks, 256>>>(xh, ah);
    mma_gemm<true, true, false, true><<<gemmGrid, 256, SMEMSZ>>>(
        ah, wtf + 0 * 65536, xh, wtf + 1 * 65536, b1, nullptr, h1h);

    // ---- layer 2 ----
    aggregate_kernel<<<aggBlocks, 256>>>(h1h, ah);
    mma_gemm<true, true, false, true><<<gemmGrid, 256, SMEMSZ>>>(
        ah, wtf + 2 * 65536, h1h, wtf + 3 * 65536, b2, nullptr, h2h);

    // ---- head ----
    mma_gemm<false, false, true, false><<<gemmGrid, 256, SMEMSZ>>>(
        h2h, wtf + 4 * 65536, nullptr, nullptr, b3, out, nullptr);
}